// round 2
// baseline (speedup 1.0000x reference)
#include <cuda_runtime.h>
#include <cuda_bf16.h>

// RandomShiftsAug collapsed to a single gather:
//   out[n,c,i,j] = x[n, c, wrap(max(ky+i-4,0)), clamp(kx+j-4,0,419)]
// x: (128, 9, 84, 420) fp32, shift: (128, 2) int32 (kx = shift[:,0], ky = shift[:,1])
// out: (128, 9, 84, 420) fp32
//
// Derivation: h(=84) != w(=420) so reference tiles H by 5 -> (128,9,420,420),
// edge-pads by 4, crops (9,84,420) at (ky,kx), ky,kx in [0,8].
//   row:  src_r = ky + i - 4 clamped below at 0 (edge pad); values 84..87 wrap
//         into the tiled copy -> subtract 84 once.
//   col:  src_c = clamp(kx + j - 4, 0, 419) (edge pad on both sides).

#define N_BATCH 128
#define N_CH 9
#define H 84
#define W 420
#define W4 105                             // W / 4 float4 per row
#define N_ROWS (N_BATCH * N_CH * H)        // 96768
#define N_VEC  (N_ROWS * W4)               // 10160640 float4 stores

__global__ __launch_bounds__(256) void RandomShiftsAug_59115929862159_kernel(
    const float* __restrict__ x,
    const int2*  __restrict__ shift,       // shift[n] = (kx, ky)
    float4*      __restrict__ out)
{
    int idx = blockIdx.x * blockDim.x + threadIdx.x;
    if (idx >= N_VEC) return;

    int row = idx / W4;            // output row id in [0, 96768)
    int c4  = idx - row * W4;      // float4 column in [0, 105)

    int i  = row % H;              // output row within image
    int nc = row / H;              // (n*9 + c)
    int n  = nc / N_CH;

    int2 s  = __ldg(&shift[n]);
    int  kx = s.x;
    int  ky = s.y;

    // source row: wrap(max(ky + i - 4, 0)); ky+i-4 in [-4, 87]
    int r = ky + i - 4;
    r = max(r, 0);
    if (r >= H) r -= H;            // r <= 87, so one subtract wraps the tile

    const float* src = x + (size_t)(nc * H + r) * W;

    int j  = c4 << 2;              // first output column of this float4
    int dx = kx - 4;               // column shift in [-4, 4]

    // 4 independent scalar gathers (misaligned-by-dx source; clamp at edges).
    // Consecutive threads hit consecutive addresses -> sector-coalesced
    // (at most 17/16 sectors per warp-row when dx != 0).
    int j0 = min(max(j + 0 + dx, 0), W - 1);
    int j1 = min(max(j + 1 + dx, 0), W - 1);
    int j2 = min(max(j + 2 + dx, 0), W - 1);
    int j3 = min(max(j + 3 + dx, 0), W - 1);

    float4 v;
    v.x = __ldg(src + j0);
    v.y = __ldg(src + j1);
    v.z = __ldg(src + j2);
    v.w = __ldg(src + j3);

    out[idx] = v;
}

extern "C" void kernel_launch(void* const* d_in, const int* in_sizes, int n_in,
                              void* d_out, int out_size)
{
    const float* x     = (const float*)d_in[0];
    const int2*  shift = (const int2*)d_in[1];
    float4*      out   = (float4*)d_out;

    const int threads = 256;
    const int blocks  = (N_VEC + threads - 1) / threads;   // 39690
    RandomShiftsAug_59115929862159_kernel<<<blocks, threads>>>(x, shift, out);
}